// round 1
// baseline (speedup 1.0000x reference)
#include <cuda_runtime.h>
#include <cstdint>

#define KK 3
#define CIN 64
#define COUT 64
#define HH 128
#define WW 128
#define BB 4
#define SLAB 4104          // floats per h-slab in smem: 4096 + 8 pad (bank offset 8)
#define IN_XPAD 132        // 128 + halo(2) + pad(2)
#define NTHREADS 256

// Transposed weights: [tap][h][c][o], tap = ky*3+kx
__device__ float g_wt[9 * 3 * CIN * COUT];

__global__ void transpose_w_kernel(const float* __restrict__ w) {
    int idx = blockIdx.x * blockDim.x + threadIdx.x;
    if (idx >= 9 * 3 * CIN * COUT) return;
    int o   = idx & 63;
    int c   = (idx >> 6) & 63;
    int h   = (idx >> 12) % 3;
    int tap = idx / (3 * CIN * COUT);
    // weight layout: [h][o][c][ky][kx] -> flat ((h*64+o)*64+c)*9 + tap
    g_wt[idx] = w[(((h * COUT + o) * CIN + c) * 9) + tap];
}

// accumulate 64-channel dot for one tap with per-lane h selection (h==3 -> zero slab)
__device__ __forceinline__ void accumulate_tap(unsigned long long acc[16],
                                               const float* __restrict__ s_w,
                                               const float* __restrict__ inrow,
                                               int h, int og) {
    const float* wbase = s_w + h * SLAB + og * 32;
#pragma unroll 4
    for (int c = 0; c < CIN; c++) {
        float iv = inrow[c * IN_XPAD];
        unsigned long long iv2;
        asm("mov.b64 %0, {%1, %1};" : "=l"(iv2) : "f"(iv));
        const ulonglong2* wp = reinterpret_cast<const ulonglong2*>(wbase + c * COUT);
#pragma unroll
        for (int i = 0; i < 8; i++) {
            ulonglong2 wv = wp[i];
            asm("fma.rn.f32x2 %0, %1, %2, %0;" : "+l"(acc[2 * i])     : "l"(wv.x), "l"(iv2));
            asm("fma.rn.f32x2 %0, %1, %2, %0;" : "+l"(acc[2 * i + 1]) : "l"(wv.y), "l"(iv2));
        }
    }
}

__global__ __launch_bounds__(NTHREADS, 1)
void conv25d_kernel(const float* __restrict__ inp, const float* __restrict__ dep,
                    const float* __restrict__ bias, const void* __restrict__ fptr,
                    float* __restrict__ out) {
    extern __shared__ float smem[];
    float* s_in = smem;                       // [3][CIN][IN_XPAD]
    float* s_w  = s_in + 3 * CIN * IN_XPAD;   // [4][SLAB]  (slab 3 = zeros)
    float* s_d  = s_w + 4 * SLAB;             // [3][IN_XPAD]

    const int tid = threadIdx.x;
    const int y   = blockIdx.x;
    const int b   = blockIdx.y;
    const int x   = tid & 127;     // pixel column, lane dim
    const int og  = tid >> 7;      // output-channel half (32 each)

    // robust read of scalar f (int32 / int64 small value, or float32 bits)
    unsigned fu = *reinterpret_cast<const unsigned*>(fptr);
    float fval = (fu > 0u && fu < (1u << 24)) ? (float)fu : __uint_as_float(fu);

    // stage input rows y-1..y+1, all channels, with zero halo
    const float* inb = inp + ((long)b * CIN) * HH * WW;
    for (int i = tid; i < 3 * CIN * IN_XPAD; i += NTHREADS) {
        int xx = i % IN_XPAD;
        int c  = (i / IN_XPAD) % CIN;
        int r  = i / (IN_XPAD * CIN);
        int gx = xx - 1, gy = y + r - 1;
        float v = 0.f;
        if ((unsigned)gx < (unsigned)WW && (unsigned)gy < (unsigned)HH)
            v = inb[(c * HH + gy) * WW + gx];
        s_in[i] = v;
    }
    // stage depth rows (zero-padded, matching unfold's padding)
    const float* db = dep + (long)b * HH * WW;
    for (int i = tid; i < 3 * IN_XPAD; i += NTHREADS) {
        int xx = i % IN_XPAD, r = i / IN_XPAD;
        int gx = xx - 1, gy = y + r - 1;
        float v = 0.f;
        if ((unsigned)gx < (unsigned)WW && (unsigned)gy < (unsigned)HH)
            v = db[gy * WW + gx];
        s_d[i] = v;
    }
    // zero weight slab (index 3) for no-match lanes
    for (int i = tid; i < SLAB; i += NTHREADS) s_w[3 * SLAB + i] = 0.f;

    // accumulators: 16 f32x2 pairs over o, initialized with bias
    unsigned long long acc[16];
    {
        const float2* bp = reinterpret_cast<const float2*>(bias + og * 32);
#pragma unroll
        for (int i = 0; i < 16; i++) {
            float2 bv = bp[i];
            asm("mov.b64 %0, {%1, %2};" : "=l"(acc[i]) : "f"(bv.x), "f"(bv.y));
        }
    }

    __syncthreads();

    // per-pixel bin boundaries, replicating reference float ops exactly (no FMA contraction)
    const float d0   = s_d[IN_XPAD + x + 1];
    const float s0   = __fdiv_rn(d0, fval);
    const float half = __fmul_rn(s0, 0.5f);
    float lo[3], hi[3];
#pragma unroll
    for (int h = 0; h < 3; h++) {
        float z0 = __fadd_rn(d0, __fmul_rn((float)(h - 1), s0));
        lo[h] = __fsub_rn(z0, half);
        hi[h] = __fadd_rn(z0, half);
    }

    for (int tap = 0; tap < 9; tap++) {
        // stage this tap's weights (3 h-slabs) into smem
        {
            const float4* src = reinterpret_cast<const float4*>(g_wt + tap * 3 * CIN * COUT);
#pragma unroll 1
            for (int i = tid; i < 3 * 1024; i += NTHREADS) {
                int h  = i >> 10;
                int wi = i & 1023;
                *reinterpret_cast<float4*>(&s_w[h * SLAB + wi * 4]) = src[i];
            }
        }
        __syncthreads();

        const int ky = tap / 3, kx = tap % 3;
        float dw = s_d[ky * IN_XPAD + x + kx];
        int ha = 3, hb = 3;
#pragma unroll
        for (int h = 2; h >= 0; h--) {
            if (dw >= lo[h] && dw < hi[h]) { hb = ha; ha = h; }
        }
        const float* inrow = s_in + ky * CIN * IN_XPAD + (x + kx);

        accumulate_tap(acc, s_w, inrow, ha, og);

        // rare float-boundary overlap: reference's mask-sum double-counts, so do we
        unsigned m = __ballot_sync(0xffffffffu, hb != 3);
        if (m) accumulate_tap(acc, s_w, inrow, hb, og);

        __syncthreads();  // protect s_w before next tap overwrites
    }

    // store 32 output channels for this pixel
    float* ob = out + (((long)b * COUT + og * 32) * HH + y) * WW + x;
#pragma unroll
    for (int i = 0; i < 16; i++) {
        float vlo, vhi;
        asm("mov.b64 {%0, %1}, %2;" : "=f"(vlo), "=f"(vhi) : "l"(acc[i]));
        ob[(2 * i) * HH * WW]     = vlo;
        ob[(2 * i + 1) * HH * WW] = vhi;
    }
}

extern "C" void kernel_launch(void* const* d_in, const int* in_sizes, int n_in,
                              void* d_out, int out_size) {
    const float* inputs = (const float*)d_in[0];
    const float* depth  = (const float*)d_in[1];
    const float* weight = (const float*)d_in[2];
    const float* bias   = (const float*)d_in[3];
    const void*  f      = d_in[4];
    float* out = (float*)d_out;

    transpose_w_kernel<<<(9 * 3 * CIN * COUT + 255) / 256, 256>>>(weight);

    size_t smem_bytes = (size_t)(3 * CIN * IN_XPAD + 4 * SLAB + 3 * IN_XPAD) * sizeof(float);
    cudaFuncSetAttribute(conv25d_kernel, cudaFuncAttributeMaxDynamicSharedMemorySize,
                         (int)smem_bytes);

    dim3 grid(HH, BB);
    conv25d_kernel<<<grid, NTHREADS, smem_bytes>>>(inputs, depth, bias, f, out);
}